// round 15
// baseline (speedup 1.0000x reference)
#include <cuda_runtime.h>
#include <cuda_fp16.h>

// EpochedFutureFill == causal FIR conv, B=256, T=L=65536, via FFT of N=131072.
// Four-step decomposition: N = 256 (n1, stride 512) x 512 (n2, contiguous).
//   K1 : pack + FFT256 over n1 (16x16, one transpose, zero-half aware) + w_N twiddle
//   K2f: filter row: warp-FFT512 -> F (slot layout, scaled 1/N)
//   K23: warp-autonomous FFT512 fwd + multiply + IFFT512 + w_N^{+n2 k1} (in place)
//   K4 : IFFT256 over k1 (16x16, one transpose) + causal unpack
// R14: U as fp16 (__half2 per complex); filter row fp32 (spectrum exact).
// R15: 2 rows per block in K1/K23/K4; all row-invariant twiddle setup
// (sincosf chains, start values) hoisted out of the row loop.

namespace {
constexpr int N_FFT = 131072;
constexpr int T_LEN = 65536;
constexpr int PAIRS = 128;
constexpr int ROWS_F = 129;
constexpr float TWO_PI = 6.28318530717958647692f;
constexpr float INV_N = 1.0f / (float)N_FFT;
}

// digit-reverse for radix-4^2 of 16: slot(p) = ((p&3)<<2)|(p>>2)  (involution)
#define DR16(p) ((((p) & 3) << 2) | ((p) >> 2))

// Scratch (no cudaMalloc allowed).
__device__ __half2 g_buf16[(size_t)PAIRS * N_FFT];  // data rows, fp16 complex (67 MB)
__device__ float2 g_bufF[N_FFT];                    // filter row U, fp32 (1 MB)
__device__ float4 g_fspec4[N_FFT / 2];              // F in slot layout, fp32

__device__ __forceinline__ float2 cadd(float2 a, float2 b) { return make_float2(a.x + b.x, a.y + b.y); }
__device__ __forceinline__ float2 csub(float2 a, float2 b) { return make_float2(a.x - b.x, a.y - b.y); }
__device__ __forceinline__ float2 cmul(float2 a, float2 b) {
    return make_float2(fmaf(a.x, b.x, -a.y * b.y), fmaf(a.x, b.y, a.y * b.x));
}
__device__ __forceinline__ float2 cmulc(float2 a, float2 b) {  // a * conj(b)
    return make_float2(fmaf(a.x, b.x, a.y * b.y), fmaf(a.y, b.x, -a.x * b.y));
}
template <int DIR>
__device__ __forceinline__ float2 cmuli(float2 a) {  // * (i*DIR)
    return (DIR < 0) ? make_float2(a.y, -a.x) : make_float2(-a.y, a.x);
}

// exp(-2*pi*i*j/32), compile-time after unrolling -> FFMA-imm operands.
__device__ __forceinline__ float2 w32f(int j) {
    switch (j & 15) {
        case 0:  return make_float2(1.0f, 0.0f);
        case 1:  return make_float2(0.9807852804032304f, -0.19509032201612827f);
        case 2:  return make_float2(0.9238795325112868f, -0.3826834323650898f);
        case 3:  return make_float2(0.8314696123025452f, -0.5555702330196022f);
        case 4:  return make_float2(0.7071067811865476f, -0.7071067811865476f);
        case 5:  return make_float2(0.5555702330196022f, -0.8314696123025452f);
        case 6:  return make_float2(0.3826834323650898f, -0.9238795325112868f);
        case 7:  return make_float2(0.19509032201612827f, -0.9807852804032304f);
        case 8:  return make_float2(0.0f, -1.0f);
        case 9:  return make_float2(-0.19509032201612827f, -0.9807852804032304f);
        case 10: return make_float2(-0.3826834323650898f, -0.9238795325112868f);
        case 11: return make_float2(-0.5555702330196022f, -0.8314696123025452f);
        case 12: return make_float2(-0.7071067811865476f, -0.7071067811865476f);
        case 13: return make_float2(-0.8314696123025452f, -0.5555702330196022f);
        case 14: return make_float2(-0.9238795325112868f, -0.3826834323650898f);
        default: return make_float2(-0.9807852804032304f, -0.19509032201612827f);
    }
}

template <int DIR>
__device__ __forceinline__ void dft4(float2 v[4]) {
    float2 t0 = cadd(v[0], v[2]);
    float2 t1 = cadd(v[1], v[3]);
    float2 t2 = csub(v[0], v[2]);
    float2 d  = csub(v[1], v[3]);
    v[0] = cadd(t0, t1);
    v[2] = csub(t0, t1);
    if (DIR < 0) {
        v[1] = make_float2(t2.x + d.y, t2.y - d.x);
        v[3] = make_float2(t2.x - d.y, t2.y + d.x);
    } else {
        v[1] = make_float2(t2.x - d.y, t2.y + d.x);
        v[3] = make_float2(t2.x + d.y, t2.y - d.x);
    }
}

template <int DIR>
__device__ __forceinline__ void dft16_l1_twiddle(float2 a[4], int j) {
    const float C1 = 0.92387953251128674f, S1 = 0.38268343236508978f;
    const float C2 = 0.70710678118654752f;
    const float D = (float)DIR;
    const float2 w1 = make_float2(C1, D * S1), w2 = make_float2(C2, D * C2);
    const float2 w3 = make_float2(S1, D * C1), w6 = make_float2(-C2, D * C2);
    const float2 w9 = make_float2(-C1, -D * S1);
    if (j == 1) { a[1] = cmul(a[1], w1); a[2] = cmul(a[2], w2); a[3] = cmul(a[3], w3); }
    else if (j == 2) { a[1] = cmul(a[1], w2); a[2] = cmuli<DIR>(a[2]); a[3] = cmul(a[3], w6); }
    else if (j == 3) { a[1] = cmul(a[1], w3); a[2] = cmul(a[2], w6); a[3] = cmul(a[3], w9); }
}

// In-place DIF radix-4^2 16-pt DFT. Input natural; output: slot m holds X[DR16(m)].
template <int DIR>
__device__ __forceinline__ void dft16_dif(float2 v[16]) {
#pragma unroll
    for (int j = 0; j < 4; j++) {
        float2 a[4] = {v[j], v[j + 4], v[j + 8], v[j + 12]};
        dft4<DIR>(a);
        dft16_l1_twiddle<DIR>(a, j);
        v[j] = a[0]; v[j + 4] = a[1]; v[j + 8] = a[2]; v[j + 12] = a[3];
    }
#pragma unroll
    for (int q = 0; q < 4; q++) {
        float2 a[4] = {v[4 * q], v[4 * q + 1], v[4 * q + 2], v[4 * q + 3]};
        dft4<DIR>(a);
        v[4 * q] = a[0]; v[4 * q + 1] = a[1]; v[4 * q + 2] = a[2]; v[4 * q + 3] = a[3];
    }
}

// DIF 16-pt DFT with inputs 8..15 known zero (only v[0..7] read). Output as dft16_dif.
template <int DIR>
__device__ __forceinline__ void dft16_dif_z8(float2 v[16]) {
#pragma unroll
    for (int j = 0; j < 4; j++) {
        float2 in0 = v[j], in1 = v[j + 4];
        float2 a[4];
        a[0] = cadd(in0, in1);
        a[2] = csub(in0, in1);
        if (DIR < 0) {
            a[1] = make_float2(in0.x + in1.y, in0.y - in1.x);
            a[3] = make_float2(in0.x - in1.y, in0.y + in1.x);
        } else {
            a[1] = make_float2(in0.x - in1.y, in0.y + in1.x);
            a[3] = make_float2(in0.x + in1.y, in0.y - in1.x);
        }
        dft16_l1_twiddle<DIR>(a, j);
        v[j] = a[0]; v[j + 4] = a[1]; v[j + 8] = a[2]; v[j + 12] = a[3];
    }
#pragma unroll
    for (int q = 0; q < 4; q++) {
        float2 a[4] = {v[4 * q], v[4 * q + 1], v[4 * q + 2], v[4 * q + 3]};
        dft4<DIR>(a);
        v[4 * q] = a[0]; v[4 * q + 1] = a[1]; v[4 * q + 2] = a[2]; v[4 * q + 3] = a[3];
    }
}

// In-place DIT radix-4^2 16-pt DFT. Input: slot m holds in[DR16(m)]. Output NATURAL.
template <int DIR>
__device__ __forceinline__ void dft16_dit(float2 v[16]) {
#pragma unroll
    for (int q = 0; q < 4; q++) {
        float2 a[4] = {v[4 * q], v[4 * q + 1], v[4 * q + 2], v[4 * q + 3]};
        dft4<DIR>(a);
        dft16_l1_twiddle<DIR>(a, q);
        v[4 * q] = a[0]; v[4 * q + 1] = a[1]; v[4 * q + 2] = a[2]; v[4 * q + 3] = a[3];
    }
#pragma unroll
    for (int u = 0; u < 4; u++) {
        float2 a[4] = {v[u], v[u + 4], v[u + 8], v[u + 12]};
        dft4<DIR>(a);
        v[u] = a[0]; v[u + 4] = a[1]; v[u + 8] = a[2]; v[u + 12] = a[3];
    }
}

__device__ __forceinline__ float2 shflx1(float2 a) {
    return make_float2(__shfl_xor_sync(0xffffffffu, a.x, 1),
                       __shfl_xor_sync(0xffffffffu, a.y, 1));
}

// ---------------- warp-level 512-pt forward FFT (fp32 values in regs) ----------------
__device__ __forceinline__ void wfft512_fwd(float2 v[16], float2* sw, int lane,
                                            float2 w512p, float2 w64p, float2 w32p) {
    dft16_dif<-1>(v);  // slot m <-> freq DR16(m)
    int lo = lane & 15, hib = (lane >> 4) << 3;
#pragma unroll
    for (int p = 0; p < 16; p++) sw[(lane << 4) + (p ^ lo ^ hib)] = v[DR16(p)];
    __syncwarp();
    int p = lane >> 1, h = lane & 1;
#pragma unroll
    for (int j = 0; j < 16; j++) v[j] = sw[((16 * h + j) << 4) + (p ^ j ^ (h << 3))];
    __syncwarp();
    {   // twiddle w512^{p*(16h+j)}: two 8-deep chains (j and j+8)
        float2 c0 = h ? w32p : make_float2(1.0f, 0.0f);
        float2 c1 = cmul(c0, w64p);
#pragma unroll
        for (int j = 0; j < 8; j++) {
            v[j] = cmul(v[j], c0);
            v[j + 8] = cmul(v[j + 8], c1);
            c0 = cmul(c0, w512p);
            c1 = cmul(c1, w512p);
        }
    }
    {   // radix-2 butterfly over halves; w32^j are literals
#pragma unroll
        for (int j = 0; j < 16; j++) {
            float2 other = shflx1(v[j]);
            if (h == 0) v[j] = cadd(v[j], other);
            else if (j == 0) v[j] = csub(other, v[j]);
            else v[j] = cmul(csub(other, v[j]), w32f(j));
        }
    }
    dft16_dif<-1>(v);  // slot m <-> q' = DR16(m)
}

// ---------------- K2f: filter spectrum (fp32 path) in slot layout, scaled 1/N --------
__global__ __launch_bounds__(256, 4) void k_filter_spec(const float2* __restrict__ Uf,
                                                        float2* __restrict__ Fp) {
    __shared__ float2 sw[8][512];
    int lane = threadIdx.x & 31, w = threadIdx.x >> 5;
    int k1 = (blockIdx.x << 3) + w;
    int p = lane >> 1;
    float sA, cA, s6, c6, s0, c0;
    __sincosf(-(TWO_PI / 512.0f) * (float)p, &sA, &cA);
    __sincosf(-(TWO_PI / 64.0f) * (float)p, &s6, &c6);
    __sincosf(-(TWO_PI / 32.0f) * (float)p, &s0, &c0);
    const float2* u = Uf + (k1 << 9);
    float2 v[16];
#pragma unroll
    for (int r = 0; r < 16; r++) v[r] = u[lane + 32 * r];
    wfft512_fwd(v, sw[w], lane, make_float2(cA, sA), make_float2(c6, s6), make_float2(c0, s0));
    float2* o = Fp + (k1 << 9) + (lane << 4);
#pragma unroll
    for (int m = 0; m < 16; m++)
        o[m] = make_float2(v[m].x * INV_N, v[m].y * INV_N);
}

// ---------------- K23: fwd FFT512 + multiply + inv FFT512 + w_N^{+n2 k1} (fp16 U) -----
// 2 rows per block; all row-invariant twiddle setup hoisted.
__global__ __launch_bounds__(256, 4) void k_stageB_conv(__half2* U, const float4* __restrict__ Fp4) {
    __shared__ float2 sw[8][512];
    int lane = threadIdx.x & 31, w = threadIdx.x >> 5;
    int k1 = (blockIdx.x << 3) + w;
    float2* s = sw[w];
    int p = lane >> 1, h = lane & 1;
    // ---- row-invariant setup ----
    float sA, cA, s6, c6, s0, c0;
    __sincosf(-(TWO_PI / 512.0f) * (float)p, &sA, &cA);  // w512^p (fwd sign)
    __sincosf(-(TWO_PI / 64.0f) * (float)p, &s6, &c6);   // w64^p
    __sincosf(-(TWO_PI / 32.0f) * (float)p, &s0, &c0);   // w32^p
    float2 w512p = make_float2(cA, sA), w64p = make_float2(c6, s6), w32p = make_float2(c0, s0);
    float sb, cb, ss, cs, s8, c8;
    __sincosf((TWO_PI / (float)N_FFT) * (float)(lane * k1), &sb, &cb);
    __sincosf((TWO_PI / 4096.0f) * (float)k1, &ss, &cs);  // w_N^{+32 k1}
    __sincosf((TWO_PI / 512.0f) * (float)k1, &s8, &c8);   // w_N^{+256 k1}
    const float2 wk0_i = make_float2(cb, sb), wstep = make_float2(cs, ss);
    const float2 wk8_i = cmul(wk0_i, make_float2(c8, s8));
    const float4* Fr = Fp4 + (((k1 << 9) + (lane << 4)) >> 1);

#pragma unroll
    for (int rr = 0; rr < 2; rr++) {
        int row = (blockIdx.y << 1) + rr;
        __half2* u = U + (size_t)row * N_FFT + (k1 << 9);
        float2 v[16];
#pragma unroll
        for (int r = 0; r < 16; r++) v[r] = __half22float2(u[lane + 32 * r]);
        wfft512_fwd(v, s, lane, w512p, w64p, w32p);

        // multiply by filter spectrum (slot-aligned, 8 x LDG.128; row 2 hits L1)
#pragma unroll
        for (int m2 = 0; m2 < 8; m2++) {
            float4 f = __ldg(Fr + m2);
            v[2 * m2]     = cmul(v[2 * m2],     make_float2(f.x, f.y));
            v[2 * m2 + 1] = cmul(v[2 * m2 + 1], make_float2(f.z, f.w));
        }

        // ---- inverse ----
        dft16_dit<1>(v);  // digitrev in -> NATURAL out: v[tau]
        {   // butterfly (w32^j literals) + conj twiddle, two 8-deep cB chains
            float2 cB0 = h ? w32p : make_float2(1.0f, 0.0f);
            float2 cB1 = cmul(cB0, w64p);
#pragma unroll
            for (int j = 0; j < 8; j++) {
                {
                    float2 other = shflx1(v[j]);
                    if (h == 0) v[j] = (j == 0) ? cadd(v[j], other) : cadd(v[j], cmulc(other, w32f(j)));
                    else        v[j] = (j == 0) ? csub(other, v[j]) : csub(other, cmulc(v[j], w32f(j)));
                    v[j] = cmulc(v[j], cB0);
                    cB0 = cmul(cB0, w512p);
                }
                {
                    int j8 = j + 8;
                    float2 other = shflx1(v[j8]);
                    if (h == 0) v[j8] = cadd(v[j8], cmulc(other, w32f(j8)));
                    else        v[j8] = csub(other, cmulc(v[j8], w32f(j8)));
                    v[j8] = cmulc(v[j8], cB1);
                    cB1 = cmul(cB1, w512p);
                }
            }
        }
        __syncwarp();
#pragma unroll
        for (int j = 0; j < 16; j++) s[((j + 16 * h) << 4) + (p ^ j ^ (h << 3))] = v[j];
        __syncwarp();
        int lo = lane & 15, hib = (lane >> 4) << 3;
#pragma unroll
        for (int q = 0; q < 16; q++) v[q] = s[(lane << 4) + (q ^ lo ^ hib)];
        __syncwarp();  // protect smem before next row's fwd scatter
        dft16_dif<1>(v);  // natural in -> slot m <-> r = DR16(m); n2 = lane + 32r

        // outer twiddle w_N^{+n2 k1}: two 8-deep chains (r and r+8)
        float2 wk0 = wk0_i, wk8 = wk8_i;
#pragma unroll
        for (int r = 0; r < 8; r++) {
            u[lane + 32 * r] = __float22half2_rn(cmul(v[DR16(r)], wk0));
            u[lane + 32 * (r + 8)] = __float22half2_rn(cmul(v[DR16(r + 8)], wk8));
            wk0 = cmul(wk0, wstep);
            wk8 = cmul(wk8, wstep);
        }
    }
}

// ---------------- K1: pack + FFT256 over n1 (16x16, one transpose) + w_N twiddle ------
// 2 rows per block (grid y=65; last block handles the filter row alone).
__global__ __launch_bounds__(256, 4) void k_stageA(const float* __restrict__ x,
                                                   const float* __restrict__ filt,
                                                   __half2* __restrict__ U16,
                                                   float2* __restrict__ Uf) {
    __shared__ float2 sm[16][16][16];  // [t][k0][swizzled c]
    int tx = threadIdx.x;
    int c = tx & 15, t = tx >> 4;
    int n2 = (blockIdx.x << 4) + c;
    // ---- row-invariant setup ----
    float sA, cA, s8, c8;
    __sincosf(-(TWO_PI / 256.0f) * (float)t, &sA, &cA);
    __sincosf(-(TWO_PI / 32.0f) * (float)t, &s8, &c8);
    const float2 stepI = make_float2(cA, sA);
    const float2 c1_i = make_float2(c8, s8);
    float sb, cb, ssx, csx, s7, c7;
    __sincosf(-(TWO_PI / (float)N_FFT) * (float)(n2 * t), &sb, &cb);
    __sincosf(-(TWO_PI / 8192.0f) * (float)n2, &ssx, &csx);  // w_N^{-16 n2}
    __sincosf(-(TWO_PI / 1024.0f) * (float)n2, &s7, &c7);    // w_N^{-128 n2}
    const float2 wk0_i = make_float2(cb, sb), wstepE = make_float2(csx, ssx);
    const float2 wk8_i = cmul(wk0_i, make_float2(c7, s7));

#pragma unroll
    for (int rr = 0; rr < 2; rr++) {
        int row = (blockIdx.y << 1) + rr;
        if (row >= ROWS_F) break;  // block-uniform
        float2 v[16];
        if (row < PAIRS) {
            const float* xa = x + (size_t)row * T_LEN;
            const float* xb = x + (size_t)(row + PAIRS) * T_LEN;
#pragma unroll
            for (int b = 0; b < 8; b++) {
                int n = ((t + 16 * b) << 9) + n2;
                v[b] = make_float2(__ldg(xa + n), __ldg(xb + n));
            }
        } else {
#pragma unroll
            for (int b = 0; b < 8; b++) {
                int n = ((t + 16 * b) << 9) + n2;
                v[b] = make_float2(__ldg(filt + n), 0.0f);
            }
        }
        dft16_dif_z8<-1>(v);  // over b: slot m <-> k0 = DR16(m)
        {   // twiddle w256^{-t k0}: two 8-deep chains
            float2 c0 = make_float2(1.0f, 0.0f);
            float2 c1 = c1_i;
#pragma unroll
            for (int k0 = 0; k0 < 8; k0++) {
                v[DR16(k0)] = cmul(v[DR16(k0)], c0);
                v[DR16(k0 + 8)] = cmul(v[DR16(k0 + 8)], c1);
                c0 = cmul(c0, stepI);
                c1 = cmul(c1, stepI);
            }
        }
        if (rr) __syncthreads();  // smem reuse across rows
#pragma unroll
        for (int k0 = 0; k0 < 16; k0++)
            sm[t][k0][(c + 8 * ((t + k0) & 1)) & 15] = v[DR16(k0)];
        __syncthreads();
#pragma unroll
        for (int a = 0; a < 16; a++)
            v[a] = sm[a][t][(c + 8 * ((a + t) & 1)) & 15];
        dft16_dif<-1>(v);  // over a: slot m <-> k1o = DR16(m); k1 = t + 16*k1o

        float2 wk0 = wk0_i, wk8 = wk8_i;
        if (row < PAIRS) {
            __half2* Ur = U16 + (size_t)row * N_FFT + n2;
#pragma unroll
            for (int k1o = 0; k1o < 8; k1o++) {
                Ur[(t + 16 * k1o) << 9] = __float22half2_rn(cmul(v[DR16(k1o)], wk0));
                Ur[(t + 16 * (k1o + 8)) << 9] = __float22half2_rn(cmul(v[DR16(k1o + 8)], wk8));
                wk0 = cmul(wk0, wstepE);
                wk8 = cmul(wk8, wstepE);
            }
        } else {
            float2* Ur = Uf + n2;
#pragma unroll
            for (int k1o = 0; k1o < 8; k1o++) {
                Ur[(t + 16 * k1o) << 9] = cmul(v[DR16(k1o)], wk0);
                Ur[(t + 16 * (k1o + 8)) << 9] = cmul(v[DR16(k1o + 8)], wk8);
                wk0 = cmul(wk0, wstepE);
                wk8 = cmul(wk8, wstepE);
            }
        }
    }
}

// ---------------- K4: IFFT256 over k1 (16x16, one transpose) + causal unpack --------
// 2 rows per block.
__global__ __launch_bounds__(256, 4) void k_stageAinv(const __half2* __restrict__ U,
                                                      float* __restrict__ y) {
    __shared__ float2 sm[16][16][16];  // [t][ni][swizzled c]
    int tx = threadIdx.x;
    int c = tx & 15, t = tx >> 4;
    int n2 = (blockIdx.x << 4) + c;
    // ---- row-invariant setup ----
    float sA, cA, s8, c8;
    __sincosf(-(TWO_PI / 256.0f) * (float)t, &sA, &cA);
    __sincosf(-(TWO_PI / 32.0f) * (float)t, &s8, &c8);
    const float2 stepI = make_float2(cA, sA);
    const float2 c1_i = make_float2(c8, s8);

#pragma unroll
    for (int rr = 0; rr < 2; rr++) {
        int row = (blockIdx.y << 1) + rr;
        const __half2* u = U + (size_t)row * N_FFT + n2;
        float2 v[16];
#pragma unroll
        for (int s = 0; s < 16; s++) v[s] = __half22float2(__ldg(u + (size_t)((t + 16 * s) << 9)));
        dft16_dif<1>(v);  // inverse inner over s: slot m <-> ni = DR16(m)
        {   // twiddle w256^{+ni t}: two 8-deep chains
            float2 c0 = make_float2(1.0f, 0.0f);
            float2 c1 = c1_i;
#pragma unroll
            for (int ni = 0; ni < 8; ni++) {
                v[DR16(ni)] = cmulc(v[DR16(ni)], c0);
                v[DR16(ni + 8)] = cmulc(v[DR16(ni + 8)], c1);
                c0 = cmul(c0, stepI);
                c1 = cmul(c1, stepI);
            }
        }
        if (rr) __syncthreads();  // smem reuse across rows
#pragma unroll
        for (int ni = 0; ni < 16; ni++)
            sm[t][ni][(c + 8 * ((t + ni) & 1)) & 15] = v[DR16(ni)];
        __syncthreads();
#pragma unroll
        for (int tt = 0; tt < 16; tt++)
            v[tt] = sm[tt][t][(c + 8 * ((tt + t) & 1)) & 15];
        dft16_dif<1>(v);  // inverse outer over t: slot m <-> no = DR16(m)

        float* ya = y + (size_t)row * T_LEN;
        float* yb = y + (size_t)(row + PAIRS) * T_LEN;
#pragma unroll
        for (int no = 0; no < 8; no++) {  // n1 = t + 16*no < 128
            int n = ((t + 16 * no) << 9) + n2;
            float2 q = v[DR16(no)];
            ya[n] = q.x;
            yb[n] = q.y;
        }
    }
}

extern "C" void kernel_launch(void* const* d_in, const int* in_sizes, int n_in,
                              void* d_out, int out_size) {
    const float* x = (const float*)d_in[0];
    const float* filt = (const float*)d_in[1];
    float* y = (float*)d_out;

    __half2* U16 = nullptr;
    float2* Uf = nullptr;
    float4* F4 = nullptr;
    cudaGetSymbolAddress((void**)&U16, g_buf16);
    cudaGetSymbolAddress((void**)&Uf, g_bufF);
    cudaGetSymbolAddress((void**)&F4, g_fspec4);

    k_stageA<<<dim3(32, (ROWS_F + 1) / 2), 256>>>(x, filt, U16, Uf);
    k_filter_spec<<<32, 256>>>(Uf, (float2*)F4);
    k_stageB_conv<<<dim3(32, PAIRS / 2), 256>>>(U16, F4);
    k_stageAinv<<<dim3(32, PAIRS / 2), 256>>>(U16, y);
}

// round 16
// speedup vs baseline: 1.5562x; 1.5562x over previous
#include <cuda_runtime.h>
#include <cuda_fp16.h>

// EpochedFutureFill == causal FIR conv, B=256, T=L=65536, via FFT of N=131072.
// Four-step decomposition: N = 256 (n1, stride 512) x 512 (n2, contiguous).
//   K1 : pack + FFT256 over n1 (16x16, one transpose, zero-half aware) + w_N twiddle
//   K2f: filter row: warp-FFT512 -> F (slot layout, scaled 1/N)
//   K23: warp-autonomous FFT512 fwd + multiply + IFFT512 + w_N^{+n2 k1} (in place)
//   K4 : IFFT256 over k1 (16x16, one transpose) + causal unpack
// R14 state (best: 133.6us): U as fp16; filter row fp32 (exact spectrum).
// R16: revert R15's 2-row batching (regressed: register spills); K4 y-stores
// use __stwt streaming hint (write-once data, keep L2 for U reads).

namespace {
constexpr int N_FFT = 131072;
constexpr int T_LEN = 65536;
constexpr int PAIRS = 128;
constexpr int ROWS_F = 129;
constexpr float TWO_PI = 6.28318530717958647692f;
constexpr float INV_N = 1.0f / (float)N_FFT;
}

// digit-reverse for radix-4^2 of 16: slot(p) = ((p&3)<<2)|(p>>2)  (involution)
#define DR16(p) ((((p) & 3) << 2) | ((p) >> 2))

// Scratch (no cudaMalloc allowed).
__device__ __half2 g_buf16[(size_t)PAIRS * N_FFT];  // data rows, fp16 complex (67 MB)
__device__ float2 g_bufF[N_FFT];                    // filter row U, fp32 (1 MB)
__device__ float4 g_fspec4[N_FFT / 2];              // F in slot layout, fp32

__device__ __forceinline__ float2 cadd(float2 a, float2 b) { return make_float2(a.x + b.x, a.y + b.y); }
__device__ __forceinline__ float2 csub(float2 a, float2 b) { return make_float2(a.x - b.x, a.y - b.y); }
__device__ __forceinline__ float2 cmul(float2 a, float2 b) {
    return make_float2(fmaf(a.x, b.x, -a.y * b.y), fmaf(a.x, b.y, a.y * b.x));
}
__device__ __forceinline__ float2 cmulc(float2 a, float2 b) {  // a * conj(b)
    return make_float2(fmaf(a.x, b.x, a.y * b.y), fmaf(a.y, b.x, -a.x * b.y));
}
template <int DIR>
__device__ __forceinline__ float2 cmuli(float2 a) {  // * (i*DIR)
    return (DIR < 0) ? make_float2(a.y, -a.x) : make_float2(-a.y, a.x);
}

// exp(-2*pi*i*j/32), compile-time after unrolling -> FFMA-imm operands.
__device__ __forceinline__ float2 w32f(int j) {
    switch (j & 15) {
        case 0:  return make_float2(1.0f, 0.0f);
        case 1:  return make_float2(0.9807852804032304f, -0.19509032201612827f);
        case 2:  return make_float2(0.9238795325112868f, -0.3826834323650898f);
        case 3:  return make_float2(0.8314696123025452f, -0.5555702330196022f);
        case 4:  return make_float2(0.7071067811865476f, -0.7071067811865476f);
        case 5:  return make_float2(0.5555702330196022f, -0.8314696123025452f);
        case 6:  return make_float2(0.3826834323650898f, -0.9238795325112868f);
        case 7:  return make_float2(0.19509032201612827f, -0.9807852804032304f);
        case 8:  return make_float2(0.0f, -1.0f);
        case 9:  return make_float2(-0.19509032201612827f, -0.9807852804032304f);
        case 10: return make_float2(-0.3826834323650898f, -0.9238795325112868f);
        case 11: return make_float2(-0.5555702330196022f, -0.8314696123025452f);
        case 12: return make_float2(-0.7071067811865476f, -0.7071067811865476f);
        case 13: return make_float2(-0.8314696123025452f, -0.5555702330196022f);
        case 14: return make_float2(-0.9238795325112868f, -0.3826834323650898f);
        default: return make_float2(-0.9807852804032304f, -0.19509032201612827f);
    }
}

template <int DIR>
__device__ __forceinline__ void dft4(float2 v[4]) {
    float2 t0 = cadd(v[0], v[2]);
    float2 t1 = cadd(v[1], v[3]);
    float2 t2 = csub(v[0], v[2]);
    float2 d  = csub(v[1], v[3]);
    v[0] = cadd(t0, t1);
    v[2] = csub(t0, t1);
    if (DIR < 0) {
        v[1] = make_float2(t2.x + d.y, t2.y - d.x);
        v[3] = make_float2(t2.x - d.y, t2.y + d.x);
    } else {
        v[1] = make_float2(t2.x - d.y, t2.y + d.x);
        v[3] = make_float2(t2.x + d.y, t2.y - d.x);
    }
}

template <int DIR>
__device__ __forceinline__ void dft16_l1_twiddle(float2 a[4], int j) {
    const float C1 = 0.92387953251128674f, S1 = 0.38268343236508978f;
    const float C2 = 0.70710678118654752f;
    const float D = (float)DIR;
    const float2 w1 = make_float2(C1, D * S1), w2 = make_float2(C2, D * C2);
    const float2 w3 = make_float2(S1, D * C1), w6 = make_float2(-C2, D * C2);
    const float2 w9 = make_float2(-C1, -D * S1);
    if (j == 1) { a[1] = cmul(a[1], w1); a[2] = cmul(a[2], w2); a[3] = cmul(a[3], w3); }
    else if (j == 2) { a[1] = cmul(a[1], w2); a[2] = cmuli<DIR>(a[2]); a[3] = cmul(a[3], w6); }
    else if (j == 3) { a[1] = cmul(a[1], w3); a[2] = cmul(a[2], w6); a[3] = cmul(a[3], w9); }
}

// In-place DIF radix-4^2 16-pt DFT. Input natural; output: slot m holds X[DR16(m)].
template <int DIR>
__device__ __forceinline__ void dft16_dif(float2 v[16]) {
#pragma unroll
    for (int j = 0; j < 4; j++) {
        float2 a[4] = {v[j], v[j + 4], v[j + 8], v[j + 12]};
        dft4<DIR>(a);
        dft16_l1_twiddle<DIR>(a, j);
        v[j] = a[0]; v[j + 4] = a[1]; v[j + 8] = a[2]; v[j + 12] = a[3];
    }
#pragma unroll
    for (int q = 0; q < 4; q++) {
        float2 a[4] = {v[4 * q], v[4 * q + 1], v[4 * q + 2], v[4 * q + 3]};
        dft4<DIR>(a);
        v[4 * q] = a[0]; v[4 * q + 1] = a[1]; v[4 * q + 2] = a[2]; v[4 * q + 3] = a[3];
    }
}

// DIF 16-pt DFT with inputs 8..15 known zero (only v[0..7] read). Output as dft16_dif.
template <int DIR>
__device__ __forceinline__ void dft16_dif_z8(float2 v[16]) {
#pragma unroll
    for (int j = 0; j < 4; j++) {
        float2 in0 = v[j], in1 = v[j + 4];
        float2 a[4];
        a[0] = cadd(in0, in1);
        a[2] = csub(in0, in1);
        if (DIR < 0) {
            a[1] = make_float2(in0.x + in1.y, in0.y - in1.x);
            a[3] = make_float2(in0.x - in1.y, in0.y + in1.x);
        } else {
            a[1] = make_float2(in0.x - in1.y, in0.y + in1.x);
            a[3] = make_float2(in0.x + in1.y, in0.y - in1.x);
        }
        dft16_l1_twiddle<DIR>(a, j);
        v[j] = a[0]; v[j + 4] = a[1]; v[j + 8] = a[2]; v[j + 12] = a[3];
    }
#pragma unroll
    for (int q = 0; q < 4; q++) {
        float2 a[4] = {v[4 * q], v[4 * q + 1], v[4 * q + 2], v[4 * q + 3]};
        dft4<DIR>(a);
        v[4 * q] = a[0]; v[4 * q + 1] = a[1]; v[4 * q + 2] = a[2]; v[4 * q + 3] = a[3];
    }
}

// In-place DIT radix-4^2 16-pt DFT. Input: slot m holds in[DR16(m)]. Output NATURAL.
template <int DIR>
__device__ __forceinline__ void dft16_dit(float2 v[16]) {
#pragma unroll
    for (int q = 0; q < 4; q++) {
        float2 a[4] = {v[4 * q], v[4 * q + 1], v[4 * q + 2], v[4 * q + 3]};
        dft4<DIR>(a);
        dft16_l1_twiddle<DIR>(a, q);
        v[4 * q] = a[0]; v[4 * q + 1] = a[1]; v[4 * q + 2] = a[2]; v[4 * q + 3] = a[3];
    }
#pragma unroll
    for (int u = 0; u < 4; u++) {
        float2 a[4] = {v[u], v[u + 4], v[u + 8], v[u + 12]};
        dft4<DIR>(a);
        v[u] = a[0]; v[u + 4] = a[1]; v[u + 8] = a[2]; v[u + 12] = a[3];
    }
}

__device__ __forceinline__ float2 shflx1(float2 a) {
    return make_float2(__shfl_xor_sync(0xffffffffu, a.x, 1),
                       __shfl_xor_sync(0xffffffffu, a.y, 1));
}

// ---------------- warp-level 512-pt forward FFT (fp32 values in regs) ----------------
__device__ __forceinline__ void wfft512_fwd(float2 v[16], float2* sw, int lane,
                                            float2 w512p, float2 w64p, float2 w32p) {
    dft16_dif<-1>(v);  // slot m <-> freq DR16(m)
    int lo = lane & 15, hib = (lane >> 4) << 3;
#pragma unroll
    for (int p = 0; p < 16; p++) sw[(lane << 4) + (p ^ lo ^ hib)] = v[DR16(p)];
    __syncwarp();
    int p = lane >> 1, h = lane & 1;
#pragma unroll
    for (int j = 0; j < 16; j++) v[j] = sw[((16 * h + j) << 4) + (p ^ j ^ (h << 3))];
    __syncwarp();
    {   // twiddle w512^{p*(16h+j)}: two 8-deep chains (j and j+8)
        float2 c0 = h ? w32p : make_float2(1.0f, 0.0f);
        float2 c1 = cmul(c0, w64p);
#pragma unroll
        for (int j = 0; j < 8; j++) {
            v[j] = cmul(v[j], c0);
            v[j + 8] = cmul(v[j + 8], c1);
            c0 = cmul(c0, w512p);
            c1 = cmul(c1, w512p);
        }
    }
    {   // radix-2 butterfly over halves; w32^j are literals
#pragma unroll
        for (int j = 0; j < 16; j++) {
            float2 other = shflx1(v[j]);
            if (h == 0) v[j] = cadd(v[j], other);
            else if (j == 0) v[j] = csub(other, v[j]);
            else v[j] = cmul(csub(other, v[j]), w32f(j));
        }
    }
    dft16_dif<-1>(v);  // slot m <-> q' = DR16(m)
}

// ---------------- K2f: filter spectrum (fp32 path) in slot layout, scaled 1/N --------
__global__ __launch_bounds__(256, 4) void k_filter_spec(const float2* __restrict__ Uf,
                                                        float2* __restrict__ Fp) {
    __shared__ float2 sw[8][512];
    int lane = threadIdx.x & 31, w = threadIdx.x >> 5;
    int k1 = (blockIdx.x << 3) + w;
    int p = lane >> 1;
    float sA, cA, s6, c6, s0, c0;
    __sincosf(-(TWO_PI / 512.0f) * (float)p, &sA, &cA);
    __sincosf(-(TWO_PI / 64.0f) * (float)p, &s6, &c6);
    __sincosf(-(TWO_PI / 32.0f) * (float)p, &s0, &c0);
    const float2* u = Uf + (k1 << 9);
    float2 v[16];
#pragma unroll
    for (int r = 0; r < 16; r++) v[r] = u[lane + 32 * r];
    wfft512_fwd(v, sw[w], lane, make_float2(cA, sA), make_float2(c6, s6), make_float2(c0, s0));
    float2* o = Fp + (k1 << 9) + (lane << 4);
#pragma unroll
    for (int m = 0; m < 16; m++)
        o[m] = make_float2(v[m].x * INV_N, v[m].y * INV_N);
}

// ---------------- K23: fwd FFT512 + multiply + inv FFT512 + w_N^{+n2 k1} (fp16 U) -----
__global__ __launch_bounds__(256, 4) void k_stageB_conv(__half2* U, const float4* __restrict__ Fp4) {
    __shared__ float2 sw[8][512];
    int lane = threadIdx.x & 31, w = threadIdx.x >> 5;
    int k1 = (blockIdx.x << 3) + w;
    int row = blockIdx.y;
    __half2* u = U + (size_t)row * N_FFT + (k1 << 9);
    float2* s = sw[w];
    int p = lane >> 1, h = lane & 1;
    float sA, cA, s6, c6, s0, c0;
    __sincosf(-(TWO_PI / 512.0f) * (float)p, &sA, &cA);  // w512^p (fwd sign)
    __sincosf(-(TWO_PI / 64.0f) * (float)p, &s6, &c6);   // w64^p = w512^{8p}
    __sincosf(-(TWO_PI / 32.0f) * (float)p, &s0, &c0);   // w32^p = w512^{16p}
    float2 w512p = make_float2(cA, sA), w64p = make_float2(c6, s6), w32p = make_float2(c0, s0);

    float2 v[16];
#pragma unroll
    for (int r = 0; r < 16; r++) v[r] = __half22float2(u[lane + 32 * r]);
    wfft512_fwd(v, s, lane, w512p, w64p, w32p);

    // multiply by filter spectrum (slot-aligned, 8 x LDG.128)
    const float4* Fr = Fp4 + (((k1 << 9) + (lane << 4)) >> 1);
#pragma unroll
    for (int m2 = 0; m2 < 8; m2++) {
        float4 f = __ldg(Fr + m2);
        v[2 * m2]     = cmul(v[2 * m2],     make_float2(f.x, f.y));
        v[2 * m2 + 1] = cmul(v[2 * m2 + 1], make_float2(f.z, f.w));
    }

    // ---- inverse ----
    dft16_dit<1>(v);  // digitrev in (slot m <-> q'=DR16(m)) -> NATURAL out: v[tau]
    {   // butterfly (w32^j literals) + conj twiddle, two 8-deep cB chains
        float2 cB0 = h ? w32p : make_float2(1.0f, 0.0f);
        float2 cB1 = cmul(cB0, w64p);
#pragma unroll
        for (int j = 0; j < 8; j++) {
            {
                float2 other = shflx1(v[j]);
                if (h == 0) v[j] = (j == 0) ? cadd(v[j], other) : cadd(v[j], cmulc(other, w32f(j)));
                else        v[j] = (j == 0) ? csub(other, v[j]) : csub(other, cmulc(v[j], w32f(j)));
                v[j] = cmulc(v[j], cB0);
                cB0 = cmul(cB0, w512p);
            }
            {
                int j8 = j + 8;
                float2 other = shflx1(v[j8]);
                if (h == 0) v[j8] = cadd(v[j8], cmulc(other, w32f(j8)));
                else        v[j8] = csub(other, cmulc(v[j8], w32f(j8)));
                v[j8] = cmulc(v[j8], cB1);
                cB1 = cmul(cB1, w512p);
            }
        }
    }
    __syncwarp();
#pragma unroll
    for (int j = 0; j < 16; j++) s[((j + 16 * h) << 4) + (p ^ j ^ (h << 3))] = v[j];
    __syncwarp();
    int lo = lane & 15, hib = (lane >> 4) << 3;
#pragma unroll
    for (int q = 0; q < 16; q++) v[q] = s[(lane << 4) + (q ^ lo ^ hib)];
    dft16_dif<1>(v);  // natural in -> slot m <-> r = DR16(m); n2 = lane + 32r

    // outer twiddle w_N^{+n2 k1}: two 8-deep chains (r and r+8)
    float sb, cb, ss, cs, s8, c8;
    __sincosf((TWO_PI / (float)N_FFT) * (float)(lane * k1), &sb, &cb);
    __sincosf((TWO_PI / 4096.0f) * (float)k1, &ss, &cs);  // w_N^{+32 k1}
    __sincosf((TWO_PI / 512.0f) * (float)k1, &s8, &c8);   // w_N^{+256 k1}
    float2 wk0 = make_float2(cb, sb), wstep = make_float2(cs, ss);
    float2 wk8 = cmul(wk0, make_float2(c8, s8));
#pragma unroll
    for (int r = 0; r < 8; r++) {
        u[lane + 32 * r] = __float22half2_rn(cmul(v[DR16(r)], wk0));
        u[lane + 32 * (r + 8)] = __float22half2_rn(cmul(v[DR16(r + 8)], wk8));
        wk0 = cmul(wk0, wstep);
        wk8 = cmul(wk8, wstep);
    }
}

// ---------------- K1: pack + FFT256 over n1 (16x16, one transpose) + w_N twiddle ------
// Data rows -> fp16 U; filter row (row==PAIRS) -> fp32 Uf.
__global__ __launch_bounds__(256, 4) void k_stageA(const float* __restrict__ x,
                                                   const float* __restrict__ filt,
                                                   __half2* __restrict__ U16,
                                                   float2* __restrict__ Uf) {
    __shared__ float2 sm[16][16][16];  // [t][k0][swizzled c]
    int tx = threadIdx.x;
    int c = tx & 15, t = tx >> 4;
    int n2 = (blockIdx.x << 4) + c;
    int row = blockIdx.y;
    float2 v[16];
    if (row < PAIRS) {
        const float* xa = x + (size_t)row * T_LEN;
        const float* xb = x + (size_t)(row + PAIRS) * T_LEN;
#pragma unroll
        for (int b = 0; b < 8; b++) {
            int n = ((t + 16 * b) << 9) + n2;  // n1 = t+16b < 128
            v[b] = make_float2(__ldg(xa + n), __ldg(xb + n));
        }
    } else {
#pragma unroll
        for (int b = 0; b < 8; b++) {
            int n = ((t + 16 * b) << 9) + n2;
            v[b] = make_float2(__ldg(filt + n), 0.0f);
        }
    }
    dft16_dif_z8<-1>(v);  // over b: slot m <-> k0 = DR16(m)
    {   // twiddle w256^{-t k0}: two 8-deep chains over natural k0
        float sA, cA, s8, c8;
        __sincosf(-(TWO_PI / 256.0f) * (float)t, &sA, &cA);
        __sincosf(-(TWO_PI / 32.0f) * (float)t, &s8, &c8);
        float2 step = make_float2(cA, sA);
        float2 c0 = make_float2(1.0f, 0.0f);
        float2 c1 = make_float2(c8, s8);
#pragma unroll
        for (int k0 = 0; k0 < 8; k0++) {
            v[DR16(k0)] = cmul(v[DR16(k0)], c0);
            v[DR16(k0 + 8)] = cmul(v[DR16(k0 + 8)], c1);
            c0 = cmul(c0, step);
            c1 = cmul(c1, step);
        }
    }
#pragma unroll
    for (int k0 = 0; k0 < 16; k0++)
        sm[t][k0][(c + 8 * ((t + k0) & 1)) & 15] = v[DR16(k0)];
    __syncthreads();
#pragma unroll
    for (int a = 0; a < 16; a++)
        v[a] = sm[a][t][(c + 8 * ((a + t) & 1)) & 15];
    dft16_dif<-1>(v);  // over a: slot m <-> k1o = DR16(m); k1 = t + 16*k1o

    // epilogue: U[k1<<9 + n2] = X[k1] * w_N^{-n2 k1}; two 8-deep chains
    float sb, cb, ss, cs, s7, c7;
    __sincosf(-(TWO_PI / (float)N_FFT) * (float)(n2 * t), &sb, &cb);
    __sincosf(-(TWO_PI / 8192.0f) * (float)n2, &ss, &cs);  // w_N^{-16 n2}
    __sincosf(-(TWO_PI / 1024.0f) * (float)n2, &s7, &c7);  // w_N^{-128 n2}
    float2 wk0 = make_float2(cb, sb), wstep = make_float2(cs, ss);
    float2 wk8 = cmul(wk0, make_float2(c7, s7));
    if (row < PAIRS) {
        __half2* Ur = U16 + (size_t)row * N_FFT + n2;
#pragma unroll
        for (int k1o = 0; k1o < 8; k1o++) {
            Ur[(t + 16 * k1o) << 9] = __float22half2_rn(cmul(v[DR16(k1o)], wk0));
            Ur[(t + 16 * (k1o + 8)) << 9] = __float22half2_rn(cmul(v[DR16(k1o + 8)], wk8));
            wk0 = cmul(wk0, wstep);
            wk8 = cmul(wk8, wstep);
        }
    } else {
        float2* Ur = Uf + n2;
#pragma unroll
        for (int k1o = 0; k1o < 8; k1o++) {
            Ur[(t + 16 * k1o) << 9] = cmul(v[DR16(k1o)], wk0);
            Ur[(t + 16 * (k1o + 8)) << 9] = cmul(v[DR16(k1o + 8)], wk8);
            wk0 = cmul(wk0, wstep);
            wk8 = cmul(wk8, wstep);
        }
    }
}

// ---------------- K4: IFFT256 over k1 (16x16, one transpose) + causal unpack --------
__global__ __launch_bounds__(256, 4) void k_stageAinv(const __half2* __restrict__ U,
                                                      float* __restrict__ y) {
    __shared__ float2 sm[16][16][16];  // [t][ni][swizzled c]
    int tx = threadIdx.x;
    int c = tx & 15, t = tx >> 4;
    int n2 = (blockIdx.x << 4) + c;
    int row = blockIdx.y;
    const __half2* u = U + (size_t)row * N_FFT + n2;
    float2 v[16];
#pragma unroll
    for (int s = 0; s < 16; s++) v[s] = __half22float2(__ldg(u + (size_t)((t + 16 * s) << 9)));
    dft16_dif<1>(v);  // inverse inner over s: slot m <-> ni = DR16(m)
    {   // twiddle w256^{+ni t}: two 8-deep chains over natural ni
        float sA, cA, s8, c8;
        __sincosf(-(TWO_PI / 256.0f) * (float)t, &sA, &cA);
        __sincosf(-(TWO_PI / 32.0f) * (float)t, &s8, &c8);
        float2 step = make_float2(cA, sA);
        float2 c0 = make_float2(1.0f, 0.0f);
        float2 c1 = make_float2(c8, s8);
#pragma unroll
        for (int ni = 0; ni < 8; ni++) {
            v[DR16(ni)] = cmulc(v[DR16(ni)], c0);
            v[DR16(ni + 8)] = cmulc(v[DR16(ni + 8)], c1);
            c0 = cmul(c0, step);
            c1 = cmul(c1, step);
        }
    }
#pragma unroll
    for (int ni = 0; ni < 16; ni++)
        sm[t][ni][(c + 8 * ((t + ni) & 1)) & 15] = v[DR16(ni)];
    __syncthreads();
#pragma unroll
    for (int tt = 0; tt < 16; tt++)
        v[tt] = sm[tt][t][(c + 8 * ((tt + t) & 1)) & 15];
    dft16_dif<1>(v);  // inverse outer over t: slot m <-> no = DR16(m)

    float* ya = y + (size_t)row * T_LEN;
    float* yb = y + (size_t)(row + PAIRS) * T_LEN;
#pragma unroll
    for (int no = 0; no < 8; no++) {  // n1 = t + 16*no < 128
        int n = ((t + 16 * no) << 9) + n2;
        float2 q = v[DR16(no)];
        __stwt(ya + n, q.x);
        __stwt(yb + n, q.y);
    }
}

extern "C" void kernel_launch(void* const* d_in, const int* in_sizes, int n_in,
                              void* d_out, int out_size) {
    const float* x = (const float*)d_in[0];
    const float* filt = (const float*)d_in[1];
    float* y = (float*)d_out;

    __half2* U16 = nullptr;
    float2* Uf = nullptr;
    float4* F4 = nullptr;
    cudaGetSymbolAddress((void**)&U16, g_buf16);
    cudaGetSymbolAddress((void**)&Uf, g_bufF);
    cudaGetSymbolAddress((void**)&F4, g_fspec4);

    k_stageA<<<dim3(32, ROWS_F), 256>>>(x, filt, U16, Uf);
    k_filter_spec<<<32, 256>>>(Uf, (float2*)F4);
    k_stageB_conv<<<dim3(32, PAIRS), 256>>>(U16, F4);
    k_stageAinv<<<dim3(32, PAIRS), 256>>>(U16, y);
}

// round 17
// speedup vs baseline: 1.5922x; 1.0231x over previous
#include <cuda_runtime.h>
#include <cuda_fp16.h>

// EpochedFutureFill == causal FIR conv, B=256, T=L=65536, via FFT of N=131072.
// Four-step decomposition: N = 256 (n1, stride 512) x 512 (n2, contiguous).
//   K1 : pack + FFT256 over n1 (16x16, one transpose, zero-half aware) + w_N twiddle
//   K2f: filter row: warp-FFT512 -> F (slot layout, scaled 1/N)
//   K23: warp-autonomous FFT512 fwd + multiply + IFFT512 + w_N^{+n2 k1} (in place)
//   K4 : IFFT256 over k1 (16x16, one transpose) + causal unpack
// R14 base (best: 133.6us): U as fp16; filter row fp32 (exact spectrum).
// R17: __stwt reverted (neutral); K23's three 8-deep serial cmul twiddle chains
// split into 4-deep pairs (one extra sincosf each) to halve the RAW spines.

namespace {
constexpr int N_FFT = 131072;
constexpr int T_LEN = 65536;
constexpr int PAIRS = 128;
constexpr int ROWS_F = 129;
constexpr float TWO_PI = 6.28318530717958647692f;
constexpr float INV_N = 1.0f / (float)N_FFT;
}

// digit-reverse for radix-4^2 of 16: slot(p) = ((p&3)<<2)|(p>>2)  (involution)
#define DR16(p) ((((p) & 3) << 2) | ((p) >> 2))

// Scratch (no cudaMalloc allowed).
__device__ __half2 g_buf16[(size_t)PAIRS * N_FFT];  // data rows, fp16 complex (67 MB)
__device__ float2 g_bufF[N_FFT];                    // filter row U, fp32 (1 MB)
__device__ float4 g_fspec4[N_FFT / 2];              // F in slot layout, fp32

__device__ __forceinline__ float2 cadd(float2 a, float2 b) { return make_float2(a.x + b.x, a.y + b.y); }
__device__ __forceinline__ float2 csub(float2 a, float2 b) { return make_float2(a.x - b.x, a.y - b.y); }
__device__ __forceinline__ float2 cmul(float2 a, float2 b) {
    return make_float2(fmaf(a.x, b.x, -a.y * b.y), fmaf(a.x, b.y, a.y * b.x));
}
__device__ __forceinline__ float2 cmulc(float2 a, float2 b) {  // a * conj(b)
    return make_float2(fmaf(a.x, b.x, a.y * b.y), fmaf(a.y, b.x, -a.x * b.y));
}
template <int DIR>
__device__ __forceinline__ float2 cmuli(float2 a) {  // * (i*DIR)
    return (DIR < 0) ? make_float2(a.y, -a.x) : make_float2(-a.y, a.x);
}

// exp(-2*pi*i*j/32), compile-time after unrolling -> FFMA-imm operands.
__device__ __forceinline__ float2 w32f(int j) {
    switch (j & 15) {
        case 0:  return make_float2(1.0f, 0.0f);
        case 1:  return make_float2(0.9807852804032304f, -0.19509032201612827f);
        case 2:  return make_float2(0.9238795325112868f, -0.3826834323650898f);
        case 3:  return make_float2(0.8314696123025452f, -0.5555702330196022f);
        case 4:  return make_float2(0.7071067811865476f, -0.7071067811865476f);
        case 5:  return make_float2(0.5555702330196022f, -0.8314696123025452f);
        case 6:  return make_float2(0.3826834323650898f, -0.9238795325112868f);
        case 7:  return make_float2(0.19509032201612827f, -0.9807852804032304f);
        case 8:  return make_float2(0.0f, -1.0f);
        case 9:  return make_float2(-0.19509032201612827f, -0.9807852804032304f);
        case 10: return make_float2(-0.3826834323650898f, -0.9238795325112868f);
        case 11: return make_float2(-0.5555702330196022f, -0.8314696123025452f);
        case 12: return make_float2(-0.7071067811865476f, -0.7071067811865476f);
        case 13: return make_float2(-0.8314696123025452f, -0.5555702330196022f);
        case 14: return make_float2(-0.9238795325112868f, -0.3826834323650898f);
        default: return make_float2(-0.9807852804032304f, -0.19509032201612827f);
    }
}

template <int DIR>
__device__ __forceinline__ void dft4(float2 v[4]) {
    float2 t0 = cadd(v[0], v[2]);
    float2 t1 = cadd(v[1], v[3]);
    float2 t2 = csub(v[0], v[2]);
    float2 d  = csub(v[1], v[3]);
    v[0] = cadd(t0, t1);
    v[2] = csub(t0, t1);
    if (DIR < 0) {
        v[1] = make_float2(t2.x + d.y, t2.y - d.x);
        v[3] = make_float2(t2.x - d.y, t2.y + d.x);
    } else {
        v[1] = make_float2(t2.x - d.y, t2.y + d.x);
        v[3] = make_float2(t2.x + d.y, t2.y - d.x);
    }
}

template <int DIR>
__device__ __forceinline__ void dft16_l1_twiddle(float2 a[4], int j) {
    const float C1 = 0.92387953251128674f, S1 = 0.38268343236508978f;
    const float C2 = 0.70710678118654752f;
    const float D = (float)DIR;
    const float2 w1 = make_float2(C1, D * S1), w2 = make_float2(C2, D * C2);
    const float2 w3 = make_float2(S1, D * C1), w6 = make_float2(-C2, D * C2);
    const float2 w9 = make_float2(-C1, -D * S1);
    if (j == 1) { a[1] = cmul(a[1], w1); a[2] = cmul(a[2], w2); a[3] = cmul(a[3], w3); }
    else if (j == 2) { a[1] = cmul(a[1], w2); a[2] = cmuli<DIR>(a[2]); a[3] = cmul(a[3], w6); }
    else if (j == 3) { a[1] = cmul(a[1], w3); a[2] = cmul(a[2], w6); a[3] = cmul(a[3], w9); }
}

// In-place DIF radix-4^2 16-pt DFT. Input natural; output: slot m holds X[DR16(m)].
template <int DIR>
__device__ __forceinline__ void dft16_dif(float2 v[16]) {
#pragma unroll
    for (int j = 0; j < 4; j++) {
        float2 a[4] = {v[j], v[j + 4], v[j + 8], v[j + 12]};
        dft4<DIR>(a);
        dft16_l1_twiddle<DIR>(a, j);
        v[j] = a[0]; v[j + 4] = a[1]; v[j + 8] = a[2]; v[j + 12] = a[3];
    }
#pragma unroll
    for (int q = 0; q < 4; q++) {
        float2 a[4] = {v[4 * q], v[4 * q + 1], v[4 * q + 2], v[4 * q + 3]};
        dft4<DIR>(a);
        v[4 * q] = a[0]; v[4 * q + 1] = a[1]; v[4 * q + 2] = a[2]; v[4 * q + 3] = a[3];
    }
}

// DIF 16-pt DFT with inputs 8..15 known zero (only v[0..7] read). Output as dft16_dif.
template <int DIR>
__device__ __forceinline__ void dft16_dif_z8(float2 v[16]) {
#pragma unroll
    for (int j = 0; j < 4; j++) {
        float2 in0 = v[j], in1 = v[j + 4];
        float2 a[4];
        a[0] = cadd(in0, in1);
        a[2] = csub(in0, in1);
        if (DIR < 0) {
            a[1] = make_float2(in0.x + in1.y, in0.y - in1.x);
            a[3] = make_float2(in0.x - in1.y, in0.y + in1.x);
        } else {
            a[1] = make_float2(in0.x - in1.y, in0.y + in1.x);
            a[3] = make_float2(in0.x + in1.y, in0.y - in1.x);
        }
        dft16_l1_twiddle<DIR>(a, j);
        v[j] = a[0]; v[j + 4] = a[1]; v[j + 8] = a[2]; v[j + 12] = a[3];
    }
#pragma unroll
    for (int q = 0; q < 4; q++) {
        float2 a[4] = {v[4 * q], v[4 * q + 1], v[4 * q + 2], v[4 * q + 3]};
        dft4<DIR>(a);
        v[4 * q] = a[0]; v[4 * q + 1] = a[1]; v[4 * q + 2] = a[2]; v[4 * q + 3] = a[3];
    }
}

// In-place DIT radix-4^2 16-pt DFT. Input: slot m holds in[DR16(m)]. Output NATURAL.
template <int DIR>
__device__ __forceinline__ void dft16_dit(float2 v[16]) {
#pragma unroll
    for (int q = 0; q < 4; q++) {
        float2 a[4] = {v[4 * q], v[4 * q + 1], v[4 * q + 2], v[4 * q + 3]};
        dft4<DIR>(a);
        dft16_l1_twiddle<DIR>(a, q);
        v[4 * q] = a[0]; v[4 * q + 1] = a[1]; v[4 * q + 2] = a[2]; v[4 * q + 3] = a[3];
    }
#pragma unroll
    for (int u = 0; u < 4; u++) {
        float2 a[4] = {v[u], v[u + 4], v[u + 8], v[u + 12]};
        dft4<DIR>(a);
        v[u] = a[0]; v[u + 4] = a[1]; v[u + 8] = a[2]; v[u + 12] = a[3];
    }
}

__device__ __forceinline__ float2 shflx1(float2 a) {
    return make_float2(__shfl_xor_sync(0xffffffffu, a.x, 1),
                       __shfl_xor_sync(0xffffffffu, a.y, 1));
}

// ---------------- warp-level 512-pt forward FFT (fp32 values in regs) ----------------
// w128p = w512^{4p} for the 4-way chain split.
__device__ __forceinline__ void wfft512_fwd(float2 v[16], float2* sw, int lane,
                                            float2 w512p, float2 w128p,
                                            float2 w64p, float2 w32p) {
    dft16_dif<-1>(v);  // slot m <-> freq DR16(m)
    int lo = lane & 15, hib = (lane >> 4) << 3;
#pragma unroll
    for (int p = 0; p < 16; p++) sw[(lane << 4) + (p ^ lo ^ hib)] = v[DR16(p)];
    __syncwarp();
    int p = lane >> 1, h = lane & 1;
#pragma unroll
    for (int j = 0; j < 16; j++) v[j] = sw[((16 * h + j) << 4) + (p ^ j ^ (h << 3))];
    __syncwarp();
    {   // twiddle w512^{p*(16h+j)}: four 4-deep chains (j, j+4, j+8, j+12)
        float2 c0 = h ? w32p : make_float2(1.0f, 0.0f);
        float2 c1 = cmul(c0, w128p);
        float2 c2 = cmul(c0, w64p);
        float2 c3 = cmul(c2, w128p);
#pragma unroll
        for (int j = 0; j < 4; j++) {
            v[j] = cmul(v[j], c0);
            v[j + 4] = cmul(v[j + 4], c1);
            v[j + 8] = cmul(v[j + 8], c2);
            v[j + 12] = cmul(v[j + 12], c3);
            c0 = cmul(c0, w512p);
            c1 = cmul(c1, w512p);
            c2 = cmul(c2, w512p);
            c3 = cmul(c3, w512p);
        }
    }
    {   // radix-2 butterfly over halves; w32^j are literals
#pragma unroll
        for (int j = 0; j < 16; j++) {
            float2 other = shflx1(v[j]);
            if (h == 0) v[j] = cadd(v[j], other);
            else if (j == 0) v[j] = csub(other, v[j]);
            else v[j] = cmul(csub(other, v[j]), w32f(j));
        }
    }
    dft16_dif<-1>(v);  // slot m <-> q' = DR16(m)
}

// ---------------- K2f: filter spectrum (fp32 path) in slot layout, scaled 1/N --------
__global__ __launch_bounds__(256, 4) void k_filter_spec(const float2* __restrict__ Uf,
                                                        float2* __restrict__ Fp) {
    __shared__ float2 sw[8][512];
    int lane = threadIdx.x & 31, w = threadIdx.x >> 5;
    int k1 = (blockIdx.x << 3) + w;
    int p = lane >> 1;
    float sA, cA, s5, c5, s6, c6, s0, c0;
    __sincosf(-(TWO_PI / 512.0f) * (float)p, &sA, &cA);
    __sincosf(-(TWO_PI / 128.0f) * (float)p, &s5, &c5);
    __sincosf(-(TWO_PI / 64.0f) * (float)p, &s6, &c6);
    __sincosf(-(TWO_PI / 32.0f) * (float)p, &s0, &c0);
    const float2* u = Uf + (k1 << 9);
    float2 v[16];
#pragma unroll
    for (int r = 0; r < 16; r++) v[r] = u[lane + 32 * r];
    wfft512_fwd(v, sw[w], lane, make_float2(cA, sA), make_float2(c5, s5),
                make_float2(c6, s6), make_float2(c0, s0));
    float2* o = Fp + (k1 << 9) + (lane << 4);
#pragma unroll
    for (int m = 0; m < 16; m++)
        o[m] = make_float2(v[m].x * INV_N, v[m].y * INV_N);
}

// ---------------- K23: fwd FFT512 + multiply + inv FFT512 + w_N^{+n2 k1} (fp16 U) -----
__global__ __launch_bounds__(256, 4) void k_stageB_conv(__half2* U, const float4* __restrict__ Fp4) {
    __shared__ float2 sw[8][512];
    int lane = threadIdx.x & 31, w = threadIdx.x >> 5;
    int k1 = (blockIdx.x << 3) + w;
    int row = blockIdx.y;
    __half2* u = U + (size_t)row * N_FFT + (k1 << 9);
    float2* s = sw[w];
    int p = lane >> 1, h = lane & 1;
    float sA, cA, s5, c5, s6, c6, s0, c0;
    __sincosf(-(TWO_PI / 512.0f) * (float)p, &sA, &cA);  // w512^p (fwd sign)
    __sincosf(-(TWO_PI / 128.0f) * (float)p, &s5, &c5);  // w128^p = w512^{4p}
    __sincosf(-(TWO_PI / 64.0f) * (float)p, &s6, &c6);   // w64^p  = w512^{8p}
    __sincosf(-(TWO_PI / 32.0f) * (float)p, &s0, &c0);   // w32^p  = w512^{16p}
    float2 w512p = make_float2(cA, sA), w128p = make_float2(c5, s5);
    float2 w64p = make_float2(c6, s6), w32p = make_float2(c0, s0);

    float2 v[16];
#pragma unroll
    for (int r = 0; r < 16; r++) v[r] = __half22float2(u[lane + 32 * r]);
    wfft512_fwd(v, s, lane, w512p, w128p, w64p, w32p);

    // multiply by filter spectrum (slot-aligned, 8 x LDG.128)
    const float4* Fr = Fp4 + (((k1 << 9) + (lane << 4)) >> 1);
#pragma unroll
    for (int m2 = 0; m2 < 8; m2++) {
        float4 f = __ldg(Fr + m2);
        v[2 * m2]     = cmul(v[2 * m2],     make_float2(f.x, f.y));
        v[2 * m2 + 1] = cmul(v[2 * m2 + 1], make_float2(f.z, f.w));
    }

    // ---- inverse ----
    dft16_dit<1>(v);  // digitrev in (slot m <-> q'=DR16(m)) -> NATURAL out: v[tau]
    {   // butterfly (w32^j literals) + conj twiddle, four 4-deep cB chains
        float2 cB0 = h ? w32p : make_float2(1.0f, 0.0f);
        float2 cB1 = cmul(cB0, w128p);
        float2 cB2 = cmul(cB0, w64p);
        float2 cB3 = cmul(cB2, w128p);
#pragma unroll
        for (int j = 0; j < 4; j++) {
#pragma unroll
            for (int g = 0; g < 4; g++) {
                int jj = j + 4 * g;
                float2 other = shflx1(v[jj]);
                if (h == 0) v[jj] = (jj == 0) ? cadd(v[jj], other) : cadd(v[jj], cmulc(other, w32f(jj)));
                else        v[jj] = (jj == 0) ? csub(other, v[jj]) : csub(other, cmulc(v[jj], w32f(jj)));
            }
            v[j] = cmulc(v[j], cB0);
            v[j + 4] = cmulc(v[j + 4], cB1);
            v[j + 8] = cmulc(v[j + 8], cB2);
            v[j + 12] = cmulc(v[j + 12], cB3);
            cB0 = cmul(cB0, w512p);
            cB1 = cmul(cB1, w512p);
            cB2 = cmul(cB2, w512p);
            cB3 = cmul(cB3, w512p);
        }
    }
    __syncwarp();
#pragma unroll
    for (int j = 0; j < 16; j++) s[((j + 16 * h) << 4) + (p ^ j ^ (h << 3))] = v[j];
    __syncwarp();
    int lo = lane & 15, hib = (lane >> 4) << 3;
#pragma unroll
    for (int q = 0; q < 16; q++) v[q] = s[(lane << 4) + (q ^ lo ^ hib)];
    dft16_dif<1>(v);  // natural in -> slot m <-> r = DR16(m); n2 = lane + 32r

    // outer twiddle w_N^{+n2 k1}: four 4-deep chains (r, r+4, r+8, r+12)
    float sb, cb, ss, cs, s8, c8, s4, c4;
    __sincosf((TWO_PI / (float)N_FFT) * (float)(lane * k1), &sb, &cb);
    __sincosf((TWO_PI / 4096.0f) * (float)k1, &ss, &cs);  // w_N^{+32 k1}
    __sincosf((TWO_PI / 1024.0f) * (float)k1, &s4, &c4);  // w_N^{+128 k1}
    __sincosf((TWO_PI / 512.0f) * (float)k1, &s8, &c8);   // w_N^{+256 k1}
    float2 wk0 = make_float2(cb, sb), wstep = make_float2(cs, ss);
    float2 wk4 = cmul(wk0, make_float2(c4, s4));
    float2 wk8 = cmul(wk0, make_float2(c8, s8));
    float2 wk12 = cmul(wk4, make_float2(c8, s8));
#pragma unroll
    for (int r = 0; r < 4; r++) {
        u[lane + 32 * r] = __float22half2_rn(cmul(v[DR16(r)], wk0));
        u[lane + 32 * (r + 4)] = __float22half2_rn(cmul(v[DR16(r + 4)], wk4));
        u[lane + 32 * (r + 8)] = __float22half2_rn(cmul(v[DR16(r + 8)], wk8));
        u[lane + 32 * (r + 12)] = __float22half2_rn(cmul(v[DR16(r + 12)], wk12));
        wk0 = cmul(wk0, wstep);
        wk4 = cmul(wk4, wstep);
        wk8 = cmul(wk8, wstep);
        wk12 = cmul(wk12, wstep);
    }
}

// ---------------- K1: pack + FFT256 over n1 (16x16, one transpose) + w_N twiddle ------
// Data rows -> fp16 U; filter row (row==PAIRS) -> fp32 Uf.
__global__ __launch_bounds__(256, 4) void k_stageA(const float* __restrict__ x,
                                                   const float* __restrict__ filt,
                                                   __half2* __restrict__ U16,
                                                   float2* __restrict__ Uf) {
    __shared__ float2 sm[16][16][16];  // [t][k0][swizzled c]
    int tx = threadIdx.x;
    int c = tx & 15, t = tx >> 4;
    int n2 = (blockIdx.x << 4) + c;
    int row = blockIdx.y;
    float2 v[16];
    if (row < PAIRS) {
        const float* xa = x + (size_t)row * T_LEN;
        const float* xb = x + (size_t)(row + PAIRS) * T_LEN;
#pragma unroll
        for (int b = 0; b < 8; b++) {
            int n = ((t + 16 * b) << 9) + n2;  // n1 = t+16b < 128
            v[b] = make_float2(__ldg(xa + n), __ldg(xb + n));
        }
    } else {
#pragma unroll
        for (int b = 0; b < 8; b++) {
            int n = ((t + 16 * b) << 9) + n2;
            v[b] = make_float2(__ldg(filt + n), 0.0f);
        }
    }
    dft16_dif_z8<-1>(v);  // over b: slot m <-> k0 = DR16(m)
    {   // twiddle w256^{-t k0}: two 8-deep chains over natural k0
        float sA, cA, s8, c8;
        __sincosf(-(TWO_PI / 256.0f) * (float)t, &sA, &cA);
        __sincosf(-(TWO_PI / 32.0f) * (float)t, &s8, &c8);
        float2 step = make_float2(cA, sA);
        float2 c0 = make_float2(1.0f, 0.0f);
        float2 c1 = make_float2(c8, s8);
#pragma unroll
        for (int k0 = 0; k0 < 8; k0++) {
            v[DR16(k0)] = cmul(v[DR16(k0)], c0);
            v[DR16(k0 + 8)] = cmul(v[DR16(k0 + 8)], c1);
            c0 = cmul(c0, step);
            c1 = cmul(c1, step);
        }
    }
#pragma unroll
    for (int k0 = 0; k0 < 16; k0++)
        sm[t][k0][(c + 8 * ((t + k0) & 1)) & 15] = v[DR16(k0)];
    __syncthreads();
#pragma unroll
    for (int a = 0; a < 16; a++)
        v[a] = sm[a][t][(c + 8 * ((a + t) & 1)) & 15];
    dft16_dif<-1>(v);  // over a: slot m <-> k1o = DR16(m); k1 = t + 16*k1o

    // epilogue: U[k1<<9 + n2] = X[k1] * w_N^{-n2 k1}; two 8-deep chains
    float sb, cb, ss, cs, s7, c7;
    __sincosf(-(TWO_PI / (float)N_FFT) * (float)(n2 * t), &sb, &cb);
    __sincosf(-(TWO_PI / 8192.0f) * (float)n2, &ss, &cs);  // w_N^{-16 n2}
    __sincosf(-(TWO_PI / 1024.0f) * (float)n2, &s7, &c7);  // w_N^{-128 n2}
    float2 wk0 = make_float2(cb, sb), wstep = make_float2(cs, ss);
    float2 wk8 = cmul(wk0, make_float2(c7, s7));
    if (row < PAIRS) {
        __half2* Ur = U16 + (size_t)row * N_FFT + n2;
#pragma unroll
        for (int k1o = 0; k1o < 8; k1o++) {
            Ur[(t + 16 * k1o) << 9] = __float22half2_rn(cmul(v[DR16(k1o)], wk0));
            Ur[(t + 16 * (k1o + 8)) << 9] = __float22half2_rn(cmul(v[DR16(k1o + 8)], wk8));
            wk0 = cmul(wk0, wstep);
            wk8 = cmul(wk8, wstep);
        }
    } else {
        float2* Ur = Uf + n2;
#pragma unroll
        for (int k1o = 0; k1o < 8; k1o++) {
            Ur[(t + 16 * k1o) << 9] = cmul(v[DR16(k1o)], wk0);
            Ur[(t + 16 * (k1o + 8)) << 9] = cmul(v[DR16(k1o + 8)], wk8);
            wk0 = cmul(wk0, wstep);
            wk8 = cmul(wk8, wstep);
        }
    }
}

// ---------------- K4: IFFT256 over k1 (16x16, one transpose) + causal unpack --------
__global__ __launch_bounds__(256, 4) void k_stageAinv(const __half2* __restrict__ U,
                                                      float* __restrict__ y) {
    __shared__ float2 sm[16][16][16];  // [t][ni][swizzled c]
    int tx = threadIdx.x;
    int c = tx & 15, t = tx >> 4;
    int n2 = (blockIdx.x << 4) + c;
    int row = blockIdx.y;
    const __half2* u = U + (size_t)row * N_FFT + n2;
    float2 v[16];
#pragma unroll
    for (int s = 0; s < 16; s++) v[s] = __half22float2(__ldg(u + (size_t)((t + 16 * s) << 9)));
    dft16_dif<1>(v);  // inverse inner over s: slot m <-> ni = DR16(m)
    {   // twiddle w256^{+ni t}: two 8-deep chains over natural ni
        float sA, cA, s8, c8;
        __sincosf(-(TWO_PI / 256.0f) * (float)t, &sA, &cA);
        __sincosf(-(TWO_PI / 32.0f) * (float)t, &s8, &c8);
        float2 step = make_float2(cA, sA);
        float2 c0 = make_float2(1.0f, 0.0f);
        float2 c1 = make_float2(c8, s8);
#pragma unroll
        for (int ni = 0; ni < 8; ni++) {
            v[DR16(ni)] = cmulc(v[DR16(ni)], c0);
            v[DR16(ni + 8)] = cmulc(v[DR16(ni + 8)], c1);
            c0 = cmul(c0, step);
            c1 = cmul(c1, step);
        }
    }
#pragma unroll
    for (int ni = 0; ni < 16; ni++)
        sm[t][ni][(c + 8 * ((t + ni) & 1)) & 15] = v[DR16(ni)];
    __syncthreads();
#pragma unroll
    for (int tt = 0; tt < 16; tt++)
        v[tt] = sm[tt][t][(c + 8 * ((tt + t) & 1)) & 15];
    dft16_dif<1>(v);  // inverse outer over t: slot m <-> no = DR16(m)

    float* ya = y + (size_t)row * T_LEN;
    float* yb = y + (size_t)(row + PAIRS) * T_LEN;
#pragma unroll
    for (int no = 0; no < 8; no++) {  // n1 = t + 16*no < 128
        int n = ((t + 16 * no) << 9) + n2;
        float2 q = v[DR16(no)];
        ya[n] = q.x;
        yb[n] = q.y;
    }
}

extern "C" void kernel_launch(void* const* d_in, const int* in_sizes, int n_in,
                              void* d_out, int out_size) {
    const float* x = (const float*)d_in[0];
    const float* filt = (const float*)d_in[1];
    float* y = (float*)d_out;

    __half2* U16 = nullptr;
    float2* Uf = nullptr;
    float4* F4 = nullptr;
    cudaGetSymbolAddress((void**)&U16, g_buf16);
    cudaGetSymbolAddress((void**)&Uf, g_bufF);
    cudaGetSymbolAddress((void**)&F4, g_fspec4);

    k_stageA<<<dim3(32, ROWS_F), 256>>>(x, filt, U16, Uf);
    k_filter_spec<<<32, 256>>>(Uf, (float2*)F4);
    k_stageB_conv<<<dim3(32, PAIRS), 256>>>(U16, F4);
    k_stageAinv<<<dim3(32, PAIRS), 256>>>(U16, y);
}